// round 7
// baseline (speedup 1.0000x reference)
#include <cuda_runtime.h>

static constexpr int V = 1024;
static constexpr int THREADS = 512;

__device__ float g_accum = 0.0f;
__device__ unsigned int g_done_count = 0;

__global__ void loss_kernel(const float* __restrict__ pred,
                            const int* __restrict__ tgt,
                            float* __restrict__ out, int B) {
    int i = blockIdx.x * blockDim.x + threadIdx.x;
    float v = 0.0f;
    if (i < B) {
        int t = __ldcg(&tgt[i]);
        float p = __ldcg(&pred[(size_t)i * V + t]);
        v = -__logf(p);
    }

    // intra-warp reduction
    #pragma unroll
    for (int o = 16; o > 0; o >>= 1)
        v += __shfl_down_sync(0xffffffffu, v, o);

    __shared__ float smem[THREADS >> 5];
    int lane = threadIdx.x & 31;
    int warp = threadIdx.x >> 5;
    if (lane == 0) smem[warp] = v;
    __syncthreads();

    if (warp == 0 && lane == 0) {
        #pragma unroll
        for (int w = 1; w < (THREADS >> 5); w++) v += smem[w];

        // one L2 atomic per block into the device-global accumulator
        atomicAdd(&g_accum, v);
        __threadfence();
        unsigned int prev = atomicAdd(&g_done_count, 1u);
        if (prev == (unsigned int)gridDim.x - 1u) {
            // last block: read+reset accumulator in one atomic, publish result
            float total = atomicExch(&g_accum, 0.0f);
            out[0] = total;
            g_done_count = 0;   // reset for deterministic graph replay
        }
    }
}

extern "C" void kernel_launch(void* const* d_in, const int* in_sizes, int n_in,
                              void* d_out, int out_size) {
    const float* pred = (const float*)d_in[0];
    const int* tgt = (const int*)d_in[1];
    float* out = (float*)d_out;
    int B = in_sizes[1];

    int blocks = (B + THREADS - 1) / THREADS;
    loss_kernel<<<blocks, THREADS>>>(pred, tgt, out, B);
}

// round 8
// speedup vs baseline: 1.0037x; 1.0037x over previous
#include <cuda_runtime.h>

static constexpr int V = 1024;
static constexpr int THREADS = 256;

__global__ void zero_out_kernel(float* out) {
    if (threadIdx.x == 0) out[0] = 0.0f;
}

__global__ void loss_kernel(const float* __restrict__ pred,
                            const int* __restrict__ tgt,
                            float* __restrict__ out, int B) {
    int i = blockIdx.x * blockDim.x + threadIdx.x;
    float v = 0.0f;
    if (i < B) {
        int t = __ldcg(&tgt[i]);
        float p = __ldcg(&pred[(size_t)i * V + t]);
        v = -__logf(p);
    }

    // intra-warp reduction
    #pragma unroll
    for (int o = 16; o > 0; o >>= 1)
        v += __shfl_down_sync(0xffffffffu, v, o);

    __shared__ float smem[THREADS >> 5];
    int lane = threadIdx.x & 31;
    int warp = threadIdx.x >> 5;
    if (lane == 0) smem[warp] = v;
    __syncthreads();

    if (warp == 0 && lane == 0) {
        #pragma unroll
        for (int w = 1; w < (THREADS >> 5); w++) v += smem[w];
        atomicAdd(out, v);   // one L2 atomic per block
    }
}

extern "C" void kernel_launch(void* const* d_in, const int* in_sizes, int n_in,
                              void* d_out, int out_size) {
    const float* pred = (const float*)d_in[0];
    const int* tgt = (const int*)d_in[1];
    float* out = (float*)d_out;
    int B = in_sizes[1];

    zero_out_kernel<<<1, 32>>>(out);

    int blocks = (B + THREADS - 1) / THREADS;
    loss_kernel<<<blocks, THREADS>>>(pred, tgt, out, B);
}